// round 10
// baseline (speedup 1.0000x reference)
#include <cuda_runtime.h>
#include <cstdint>

// Problem constants
#define S_LEN   64
#define D_MODEL 768
#define D_FFN   3072
#define RANK    16
#define MOD_SCALE 0.1f

// Packed f32x2 ops (ptxas won't auto-fuse from C++).
#define FMA_F32X2(d, a, b, c) \
    asm("fma.rn.f32x2 %0, %1, %2, %3;" : "=l"(d) : "l"(a), "l"(b), "l"(c))
// Duplicate a scalar float into a packed {s,s} 64-bit operand.
#define DUP_F32X2(d, s) \
    asm("mov.b64 %0, {%1, %1};" : "=l"(d) : "r"(__float_as_uint(s)))

// Device-global state. Statics are zero at first launch; the LAST block of
// each launch resets them, so every graph replay starts clean.
__device__ float    g_mod[S_LEN * RANK];
__device__ unsigned g_ctr    = 0;            // work-item claims
__device__ unsigned g_done   = 0;            // finished blocks
__device__ unsigned g_sready[S_LEN];         // per-s producer arrivals (16 each)

#define FTILE        1024
#define PAIRS_PER_CH 64
#define THREADS      256
#define N_PCHUNK     ((S_LEN * D_MODEL) / PAIRS_PER_CH)   // 768
#define N_ITEMS      (N_PCHUNK * (D_FFN / FTILE))         // 2304
#define GRID_BLOCKS  444
#define PROD_BLOCKS  128

// ---------------------------------------------------------------------------
// Fused persistent kernel.
//  Phase A (blocks 0..127): modulation, warp-per-output, then release per-s.
//  Phase B (all 444 blocks): R9 consumer — persistent work-steal with
//  claim-ahead, non-dup C smem, mov.b64 dup, 2-chain packed FFMA2,
//  streaming STG.128. Spin on g_sready[s] only before first use of each s.
//  444 blocks = 3 CTAs/SM x 148 SMs: whole grid is co-resident, so the
//  producer/consumer spin cannot deadlock.
// ---------------------------------------------------------------------------
__global__ __launch_bounds__(THREADS, 3)
void fused_kernel(const float* __restrict__ attn,
                  const float* __restrict__ A,
                  const float* __restrict__ B,
                  float* __restrict__ out)
{
    __shared__ float    Cs[PAIRS_PER_CH][RANK];
    __shared__ unsigned s_claim;

    // ---- Phase A: producers (1024 warps over first 128 blocks) -----------
    if (blockIdx.x < PROD_BLOCKS) {
        const int gw  = blockIdx.x * 8 + (threadIdx.x >> 5);  // 0..1023
        const int lid = threadIdx.x & 31;
        const int s   = gw >> 4;
        const int r   = gw & 15;

        const float* arow = attn + (size_t)s * D_MODEL;
        float acc = 0.0f;
#pragma unroll
        for (int k = 0; k < D_MODEL / 32; k++) {              // 24 iterations
            const int d = lid + 32 * k;
            acc += arow[d] * A[d * RANK + r];
        }
#pragma unroll
        for (int off = 16; off > 0; off >>= 1)
            acc += __shfl_down_sync(0xFFFFFFFFu, acc, off);

        if (lid == 0) {
            g_mod[s * RANK + r] = MOD_SCALE * tanhf(acc);
            __threadfence();                                  // release g_mod
            atomicAdd(&g_sready[s], 1u);
        }
    }

    // ---- Phase B: persistent consumer -------------------------------------
    ulonglong2 Breg[RANK];
    int prev_ftile  = -1;
    int s_done_upto = -1;   // highest s this block has confirmed ready

    if (threadIdx.x == 0) s_claim = atomicAdd(&g_ctr, 1u);
    __syncthreads();

    for (;;) {
        const unsigned idx = s_claim;
        if (idx >= N_ITEMS) break;

        // Claim-ahead: start the next atomic now; publish after compute.
        unsigned next_claim = 0u;
        if (threadIdx.x == 0) next_claim = atomicAdd(&g_ctr, 1u);

        const int ftile = (int)(idx / N_PCHUNK);              // 0..2
        const int pair0 = (int)(idx % N_PCHUNK) * PAIRS_PER_CH;
        const int f0    = ftile * FTILE + threadIdx.x * 4;
        const int sc    = pair0 / D_MODEL;                    // s of this chunk

        // Load B slab first (independent of mod; overlaps producer latency).
        if (ftile != prev_ftile) {
            prev_ftile = ftile;
#pragma unroll
            for (int r = 0; r < RANK; r++) {
                Breg[r] = *reinterpret_cast<const ulonglong2*>(&B[r * D_FFN + f0]);
            }
        }

        // Wait (once per s per block) for the producers of this s.
        if (sc > s_done_upto) {
            if (threadIdx.x == 0) {
                unsigned v;
                do {
                    asm volatile("ld.acquire.gpu.global.u32 %0, [%1];"
                                 : "=r"(v) : "l"(&g_sready[sc]) : "memory");
                } while (v < (unsigned)RANK);
            }
            s_done_upto = sc;
            __syncthreads();   // broadcast acquire to the whole block
        }

        // Build C (non-duplicated) for this chunk.
        for (int i = threadIdx.x; i < PAIRS_PER_CH * RANK; i += THREADS) {
            const int p  = i >> 4;
            const int r  = i & 15;
            const int pd = pair0 + p;
            const int s  = pd / D_MODEL;
            const int d  = pd % D_MODEL;
            Cs[p][r] = g_mod[s * RANK + r] * A[d * RANK + r];
        }
        __syncthreads();

        float* outp = out + (size_t)pair0 * D_FFN + f0;
#pragma unroll 1
        for (int p = 0; p < PAIRS_PER_CH; p++) {
            const float4* cp = reinterpret_cast<const float4*>(&Cs[p][0]);
            uint64_t a0 = 0ull;   // packed accum for {f0, f0+1}
            uint64_t a1 = 0ull;   // packed accum for {f0+2, f0+3}
#pragma unroll
            for (int i = 0; i < 4; i++) {
                const float4 c4 = cp[i];      // one broadcast LDS.128
                uint64_t d0, d1, d2, d3;
                DUP_F32X2(d0, c4.x);
                DUP_F32X2(d1, c4.y);
                DUP_F32X2(d2, c4.z);
                DUP_F32X2(d3, c4.w);
                FMA_F32X2(a0, d0, Breg[4 * i + 0].x, a0);
                FMA_F32X2(a1, d0, Breg[4 * i + 0].y, a1);
                FMA_F32X2(a0, d1, Breg[4 * i + 1].x, a0);
                FMA_F32X2(a1, d1, Breg[4 * i + 1].y, a1);
                FMA_F32X2(a0, d2, Breg[4 * i + 2].x, a0);
                FMA_F32X2(a1, d2, Breg[4 * i + 2].y, a1);
                FMA_F32X2(a0, d3, Breg[4 * i + 3].x, a0);
                FMA_F32X2(a1, d3, Breg[4 * i + 3].y, a1);
            }
            float4 v;
            v.x = __uint_as_float((uint32_t)(a0 & 0xFFFFFFFFull));
            v.y = __uint_as_float((uint32_t)(a0 >> 32));
            v.z = __uint_as_float((uint32_t)(a1 & 0xFFFFFFFFull));
            v.w = __uint_as_float((uint32_t)(a1 >> 32));
            __stcs(reinterpret_cast<float4*>(outp), v);   // streaming store
            outp += D_FFN;
        }

        if (threadIdx.x == 0) s_claim = next_claim;
        __syncthreads();
    }

    // ---- Cleanup: last block to finish resets globals for the next replay.
    __threadfence();
    if (threadIdx.x == 0) {
        if (atomicAdd(&g_done, 1u) == (unsigned)(GRID_BLOCKS - 1)) {
            g_ctr = 0u;
#pragma unroll
            for (int i = 0; i < S_LEN; i++) g_sready[i] = 0u;
            __threadfence();
            g_done = 0u;
        }
    }
}

// ---------------------------------------------------------------------------
// Launch: one kernel, one wave.
// ---------------------------------------------------------------------------
extern "C" void kernel_launch(void* const* d_in, const int* in_sizes, int n_in,
                              void* d_out, int out_size)
{
    const float* attn = (const float*)d_in[0];  // (1, 64, 768)
    const float* A    = (const float*)d_in[1];  // (768, 16)
    const float* B    = (const float*)d_in[2];  // (16, 3072)
    float* out        = (float*)d_out;          // (1, 64, 768, 3072)

    fused_kernel<<<GRID_BLOCKS, THREADS>>>(attn, A, B, out);
}